// round 12
// baseline (speedup 1.0000x reference)
#include <cuda_runtime.h>
#include <cuda_bf16.h>

typedef unsigned long long ull;

#define MT   4096
#define DD   2048
#define HH   256
#define NQ   8
#define NKV  4
#define TSEQ 2048
#define WIN  1024

// ---------------- static device scratch (no allocations) --------------------
__device__ __align__(256) float g_q[(size_t)NQ  * MT * HH];
__device__ __align__(256) float g_k[(size_t)NKV * MT * HH];
__device__ __align__(256) float g_v[(size_t)NKV * MT * HH];
__device__ __align__(256) float g_att[(size_t)MT * DD];

// ---------------- f32x2 packed helpers --------------------------------------
__device__ __forceinline__ ull pk2(float lo, float hi) {
    ull r; asm("mov.b64 %0, {%1,%2};" : "=l"(r) : "f"(lo), "f"(hi)); return r;
}
__device__ __forceinline__ float2 upk2(ull v) {
    float2 r; asm("mov.b64 {%0,%1}, %2;" : "=f"(r.x), "=f"(r.y) : "l"(v)); return r;
}
__device__ __forceinline__ void ffma2(ull& d, ull a, ull b) {
    asm("fma.rn.f32x2 %0, %1, %2, %0;" : "+l"(d) : "l"(a), "l"(b));
}
__device__ __forceinline__ ull mul2(ull a, ull b) {
    ull r; asm("mul.rn.f32x2 %0, %1, %2;" : "=l"(r) : "l"(a), "l"(b)); return r;
}

// ---------------- f32x2 SGEMM: C = A(4096x2048) @ B(2048 x N) ----------------
// 128x128x8 tile, 256 threads, 8x8 per-thread micro-tile (8 rows x 4 f32x2).
#define ASTR 132
__global__ __launch_bounds__(256, 2)
void gemm_f32x2(const float* __restrict__ A, const float* __restrict__ B0,
                float* __restrict__ C0, int ldb, int ldc,
                long bstride, long cstride)
{
    __shared__ __align__(16) float As[8 * ASTR];
    __shared__ __align__(16) float Bs[8 * 128];

    const float* B = B0 + (long)blockIdx.z * bstride;
    float*       C = C0 + (long)blockIdx.z * cstride;

    const int tid = threadIdx.x;
    const int tx  = tid & 15;
    const int ty  = tid >> 4;
    const int m0  = blockIdx.y * 128;
    const int n0  = blockIdx.x * 128;
    const int KD  = DD;

    const int ar = tid >> 1;
    const int ak = (tid & 1) * 4;
    const int br = tid >> 5;
    const int bc = (tid & 31) * 4;

    const float* Aptr = A + (long)(m0 + ar) * KD + ak;
    const float* Bptr = B + (long)br * ldb + n0 + bc;

    ull acc[8][4];
    #pragma unroll
    for (int i = 0; i < 8; i++)
        #pragma unroll
        for (int p = 0; p < 4; p++) acc[i][p] = 0ull;

    float4 a4 = *(const float4*)Aptr;
    float4 b4 = *(const float4*)Bptr;

    for (int k0 = 0; k0 < KD; k0 += 8) {
        As[(ak + 0) * ASTR + ar] = a4.x;
        As[(ak + 1) * ASTR + ar] = a4.y;
        As[(ak + 2) * ASTR + ar] = a4.z;
        As[(ak + 3) * ASTR + ar] = a4.w;
        *(float4*)&Bs[br * 128 + bc] = b4;
        __syncthreads();

        if (k0 + 8 < KD) {
            a4 = *(const float4*)(Aptr + k0 + 8);
            b4 = *(const float4*)(Bptr + (long)(k0 + 8) * ldb);
        }

        #pragma unroll
        for (int kk = 0; kk < 8; kk++) {
            float4 fa0 = *(const float4*)&As[kk * ASTR + ty * 4];
            float4 fa1 = *(const float4*)&As[kk * ASTR + ty * 4 + 64];
            ulonglong2 fb0 = *(const ulonglong2*)&Bs[kk * 128 + tx * 4];
            ulonglong2 fb1 = *(const ulonglong2*)&Bs[kk * 128 + tx * 4 + 64];
            float av[8] = {fa0.x, fa0.y, fa0.z, fa0.w, fa1.x, fa1.y, fa1.z, fa1.w};
            #pragma unroll
            for (int i = 0; i < 8; i++) {
                ull pa = pk2(av[i], av[i]);
                ffma2(acc[i][0], pa, fb0.x);
                ffma2(acc[i][1], pa, fb0.y);
                ffma2(acc[i][2], pa, fb1.x);
                ffma2(acc[i][3], pa, fb1.y);
            }
        }
        __syncthreads();
    }

    #pragma unroll
    for (int i = 0; i < 8; i++) {
        int row = m0 + ty * 4 + (i >> 2) * 64 + (i & 3);
        #pragma unroll
        for (int c = 0; c < 2; c++) {
            float2 lo = upk2(acc[i][2 * c]);
            float2 hi = upk2(acc[i][2 * c + 1]);
            float4 o = make_float4(lo.x, lo.y, hi.x, hi.y);
            *(float4*)&C[(long)row * ldc + n0 + tx * 4 + 64 * c] = o;
        }
    }
}

// ---------------- RMSNorm + RoPE + q scale (in place) ------------------------
__global__ void normrope_kernel(float* __restrict__ gq, float* __restrict__ gk,
                                const int* __restrict__ positions,
                                const float* __restrict__ qns,
                                const float* __restrict__ kns)
{
    const int m    = blockIdx.x;
    const int head = blockIdx.y;
    float* buf; const float* nsc; float omult;
    if (head < NQ) { buf = gq + ((long)head * MT + m) * HH;        nsc = qns; omult = 0.0625f; }
    else           { buf = gk + ((long)(head - NQ) * MT + m) * HH; nsc = kns; omult = 1.0f; }

    const int t = threadIdx.x;   // 64 threads
    __shared__ float row[256];
    __shared__ float red[2];

    float4 v = *(const float4*)&buf[t * 4];
    float ss = v.x * v.x + v.y * v.y + v.z * v.z + v.w * v.w;
    #pragma unroll
    for (int o = 16; o > 0; o >>= 1) ss += __shfl_xor_sync(0xffffffffu, ss, o);
    if ((t & 31) == 0) red[t >> 5] = ss;
    __syncthreads();
    float r = rsqrtf((red[0] + red[1]) * (1.0f / 256.0f) + 1e-6f);

    float4 sc = *(const float4*)&nsc[t * 4];
    row[t * 4 + 0] = v.x * r * (1.0f + sc.x);
    row[t * 4 + 1] = v.y * r * (1.0f + sc.y);
    row[t * 4 + 2] = v.z * r * (1.0f + sc.z);
    row[t * 4 + 3] = v.w * r * (1.0f + sc.w);
    __syncthreads();

    if (t < 32) {
        float pos = (float)positions[m];
        #pragma unroll
        for (int c = 0; c < 4; c++) {
            int h = t * 4 + c;                          // 0..127
            float ts = powf(10000.0f, (float)h * (1.0f / 128.0f));
            float ang = pos / ts;
            float sn, cs;
            sincosf(ang, &sn, &cs);
            float f = row[h], s = row[h + 128];
            buf[h]       = (f * cs - s * sn) * omult;
            buf[h + 128] = (s * cs + f * sn) * omult;
        }
    }
}

// ---------------- flash attention, sliding window 1024 -----------------------
// Strides MUST be multiples of 4 floats: the tile loaders use float4 on
// row*STRIDE + d offsets, and 16B alignment requires offset % 4 == 0.
// (258 was the R9/R10 misaligned-address bug: odd rows gave offset % 4 == 2.)
#define BQ    64
#define QSTR  260
#define KSTR  260
#define VSTR  260
#define PSTR  33
#define ATTN_SMEM (((BQ + 32 + 32) * 260 + BQ * PSTR) * 4)

__device__ __forceinline__ float redmax16(float v) {
    #pragma unroll
    for (int o = 8; o > 0; o >>= 1) v = fmaxf(v, __shfl_xor_sync(0xffffffffu, v, o));
    return v;
}
__device__ __forceinline__ float redsum16(float v) {
    #pragma unroll
    for (int o = 8; o > 0; o >>= 1) v += __shfl_xor_sync(0xffffffffu, v, o);
    return v;
}

__global__ __launch_bounds__(256, 1)
void attn_kernel(const float* __restrict__ qb, const float* __restrict__ kb,
                 const float* __restrict__ vb, float* __restrict__ ob)
{
    extern __shared__ __align__(16) float sm[];
    float* Qs = sm;                  // [64][260]
    float* Ks = Qs + BQ * QSTR;      // [32][260]
    float* Vs = Ks + 32 * KSTR;      // [32][260]
    float* Ps = Vs + 32 * VSTR;      // [64][33]

    const int tid = threadIdx.x;
    const int tx  = tid & 15;
    const int ty  = tid >> 4;
    const int t0  = blockIdx.x * BQ;
    const int n   = blockIdx.y;
    const int b   = blockIdx.z;
    const int kvh = n >> 1;

    const float* qptr = qb + ((long)n   * MT + b * TSEQ + t0) * HH;
    const float* kptr = kb + ((long)kvh * MT + b * TSEQ)      * HH;
    const float* vptr = vb + ((long)kvh * MT + b * TSEQ)      * HH;

    for (int e = tid * 4; e < BQ * HH; e += 1024) {
        int q = e >> 8, d = e & 255;
        *(float4*)&Qs[q * QSTR + d] = *(const float4*)&qptr[q * HH + d];
    }

    const int q0 = ty * 4;
    float mrow[4] = {-1e30f, -1e30f, -1e30f, -1e30f};
    float lrow[4] = {0.f, 0.f, 0.f, 0.f};
    ull O2[4][8];
    #pragma unroll
    for (int i = 0; i < 4; i++)
        #pragma unroll
        for (int p = 0; p < 8; p++) O2[i][p] = 0ull;

    int s_begin = t0 - (WIN - 1); if (s_begin < 0) s_begin = 0;
    s_begin &= ~31;
    const int s_end = t0 + BQ - 1;

    for (int s0 = s_begin; s0 <= s_end; s0 += 32) {
        __syncthreads();
        for (int e = tid * 4; e < 32 * HH; e += 1024) {
            int j = e >> 8, d = e & 255;
            *(float4*)&Ks[j * KSTR + d] = *(const float4*)&kptr[(long)(s0 + j) * HH + d];
            *(float4*)&Vs[j * VSTR + d] = *(const float4*)&vptr[(long)(s0 + j) * HH + d];
        }
        __syncthreads();

        // S = Q K^T (f32x2 over d-pairs); thread handles keys tx and tx+16
        ull S2[4][2];
        #pragma unroll
        for (int i = 0; i < 4; i++) { S2[i][0] = 0ull; S2[i][1] = 0ull; }
        #pragma unroll 4
        for (int d2 = 0; d2 < 128; d2++) {
            ull kp0 = *(const ull*)&Ks[tx * KSTR + 2 * d2];
            ull kp1 = *(const ull*)&Ks[(tx + 16) * KSTR + 2 * d2];
            #pragma unroll
            for (int i = 0; i < 4; i++) {
                ull qp = *(const ull*)&Qs[(q0 + i) * QSTR + 2 * d2];
                ffma2(S2[i][0], qp, kp0);
                ffma2(S2[i][1], qp, kp1);
            }
        }

        float fac[4];
        #pragma unroll
        for (int i = 0; i < 4; i++) {
            float2 f0 = upk2(S2[i][0]);
            float2 f1 = upk2(S2[i][1]);
            float sv0 = f0.x + f0.y;
            float sv1 = f1.x + f1.y;
            int t = t0 + q0 + i;
            int sA = s0 + tx, sB = s0 + tx + 16;
            bool v0 = (sA <= t) && (sA > t - WIN);
            bool v1 = (sB <= t) && (sB > t - WIN);
            if (!v0) sv0 = -1e30f;
            if (!v1) sv1 = -1e30f;

            float mx = redmax16(fmaxf(sv0, sv1));
            float mn = fmaxf(mrow[i], mx);
            fac[i] = __expf(mrow[i] - mn);
            mrow[i] = mn;
            float p0 = v0 ? __expf(sv0 - mn) : 0.f;
            float p1 = v1 ? __expf(sv1 - mn) : 0.f;
            Ps[(q0 + i) * PSTR + tx]      = p0;
            Ps[(q0 + i) * PSTR + tx + 16] = p1;
            lrow[i] = lrow[i] * fac[i] + redsum16(p0 + p1);
        }
        __syncwarp();

        // rescale O
        #pragma unroll
        for (int i = 0; i < 4; i++) {
            ull f = pk2(fac[i], fac[i]);
            #pragma unroll
            for (int p = 0; p < 8; p++) O2[i][p] = mul2(O2[i][p], f);
        }

        // O += P V ; thread owns h = tx*16 .. tx*16+15, j staggered by tx
        #pragma unroll 4
        for (int j = 0; j < 32; j++) {
            int jj = (j + tx) & 31;
            const ull* vrow = (const ull*)&Vs[jj * VSTR + tx * 16];
            ull pp[4];
            #pragma unroll
            for (int i = 0; i < 4; i++) {
                float pv = Ps[(q0 + i) * PSTR + jj];
                pp[i] = pk2(pv, pv);
            }
            #pragma unroll
            for (int p = 0; p < 8; p++) {
                ull vv = vrow[p];
                #pragma unroll
                for (int i = 0; i < 4; i++) ffma2(O2[i][p], pp[i], vv);
            }
        }
    }

    // normalize and write to g_att[m][n*256 + h]
    #pragma unroll
    for (int i = 0; i < 4; i++) {
        float inv = 1.0f / lrow[i];
        ull s = pk2(inv, inv);
        long m = (long)b * TSEQ + t0 + q0 + i;
        #pragma unroll
        for (int p = 0; p < 8; p++) {
            float2 o = upk2(mul2(O2[i][p], s));
            *(float2*)&ob[m * DD + n * HH + tx * 16 + 2 * p] = o;
        }
    }
}

// ---------------- launcher ---------------------------------------------------
extern "C" void kernel_launch(void* const* d_in, const int* in_sizes, int n_in,
                              void* d_out, int out_size) {
    const float* x    = (const float*)d_in[0];
    const int*   pos  = (const int*)  d_in[1];
    const float* q_w  = (const float*)d_in[2];
    const float* k_w  = (const float*)d_in[3];
    const float* v_w  = (const float*)d_in[4];
    const float* o_w  = (const float*)d_in[5];
    const float* qns  = (const float*)d_in[6];
    const float* kns  = (const float*)d_in[7];
    float* out = (float*)d_out;

    float *pq, *pk, *pv, *patt;
    cudaGetSymbolAddress((void**)&pq,   g_q);
    cudaGetSymbolAddress((void**)&pk,   g_k);
    cudaGetSymbolAddress((void**)&pv,   g_v);
    cudaGetSymbolAddress((void**)&patt, g_att);

    cudaFuncSetAttribute(attn_kernel,
                         cudaFuncAttributeMaxDynamicSharedMemorySize, ATTN_SMEM);

    // Q/K/V projections: per-head GEMM via grid.z
    gemm_f32x2<<<dim3(2, 32, NQ),  256>>>(x, q_w, pq, HH, HH,
                                          (long)DD * HH, (long)MT * HH);
    gemm_f32x2<<<dim3(2, 32, NKV), 256>>>(x, k_w, pk, HH, HH,
                                          (long)DD * HH, (long)MT * HH);
    gemm_f32x2<<<dim3(2, 32, NKV), 256>>>(x, v_w, pv, HH, HH,
                                          (long)DD * HH, (long)MT * HH);

    // RMSNorm + RoPE (+ q * H^-0.5)
    normrope_kernel<<<dim3(MT, NQ + NKV), 64>>>(pq, pk, pos, qns, kns);

    // windowed attention -> g_att [m][n*H+h]
    attn_kernel<<<dim3(TSEQ / BQ, NQ, 2), 256, ATTN_SMEM>>>(pq, pk, pv, patt);

    // output projection
    gemm_f32x2<<<dim3(16, 32, 1), 256>>>(patt, o_w, out, DD, DD, 0, 0);
}

// round 16
// speedup vs baseline: 1.4932x; 1.4932x over previous
#include <cuda_runtime.h>
#include <cuda_bf16.h>
#include <cstdint>

typedef unsigned long long ull;
typedef __nv_bfloat16 bf16;

#define MT   4096
#define DD   2048
#define HH   256
#define NQ   8
#define NKV  4
#define TSEQ 2048
#define WIN  1024

// ---------------- static device scratch (no allocations) --------------------
__device__ __align__(256) float g_q[(size_t)NQ  * MT * HH];
__device__ __align__(256) float g_k[(size_t)NKV * MT * HH];
__device__ __align__(256) float g_v[(size_t)NKV * MT * HH];
__device__ __align__(256) float g_att[(size_t)MT * DD];
// bf16 hi/lo split operands
__device__ __align__(256) bf16 g_xh[(size_t)MT * DD];
__device__ __align__(256) bf16 g_xl[(size_t)MT * DD];
__device__ __align__(256) bf16 g_ah[(size_t)MT * DD];
__device__ __align__(256) bf16 g_al[(size_t)MT * DD];
// transposed weights: Wt[n][k] (row = output index, K-major)
__device__ __align__(256) bf16 g_wqh[(size_t)NQ  * HH * DD];
__device__ __align__(256) bf16 g_wql[(size_t)NQ  * HH * DD];
__device__ __align__(256) bf16 g_wkh[(size_t)NKV * HH * DD];
__device__ __align__(256) bf16 g_wkl[(size_t)NKV * HH * DD];
__device__ __align__(256) bf16 g_wvh[(size_t)NKV * HH * DD];
__device__ __align__(256) bf16 g_wvl[(size_t)NKV * HH * DD];
__device__ __align__(256) bf16 g_woh[(size_t)DD * DD];
__device__ __align__(256) bf16 g_wol[(size_t)DD * DD];

// ---------------- f32x2 packed helpers (attention) --------------------------
__device__ __forceinline__ ull pk2(float lo, float hi) {
    ull r; asm("mov.b64 %0, {%1,%2};" : "=l"(r) : "f"(lo), "f"(hi)); return r;
}
__device__ __forceinline__ float2 upk2(ull v) {
    float2 r; asm("mov.b64 {%0,%1}, %2;" : "=f"(r.x), "=f"(r.y) : "l"(v)); return r;
}
__device__ __forceinline__ void ffma2(ull& d, ull a, ull b) {
    asm("fma.rn.f32x2 %0, %1, %2, %0;" : "+l"(d) : "l"(a), "l"(b));
}
__device__ __forceinline__ ull mul2(ull a, ull b) {
    ull r; asm("mul.rn.f32x2 %0, %1, %2;" : "=l"(r) : "l"(a), "l"(b)); return r;
}

// ---------------- mma.sync / ldmatrix helpers (base-target legal) ------------
#define LDSM4(r, a) \
    asm volatile("ldmatrix.sync.aligned.m8n8.x4.shared.b16 {%0,%1,%2,%3}, [%4];" \
        : "=r"((r)[0]), "=r"((r)[1]), "=r"((r)[2]), "=r"((r)[3]) : "r"(a))

#define MMA16816(c, a, b0, b1) \
    asm volatile("mma.sync.aligned.m16n8k16.row.col.f32.bf16.bf16.f32 " \
        "{%0,%1,%2,%3}, {%4,%5,%6,%7}, {%8,%9}, {%0,%1,%2,%3};" \
        : "+f"((c)[0]), "+f"((c)[1]), "+f"((c)[2]), "+f"((c)[3]) \
        : "r"((a)[0]), "r"((a)[1]), "r"((a)[2]), "r"((a)[3]), "r"(b0), "r"(b1))

// ---------------- conversion kernels -----------------------------------------
__global__ void cvt_hilo(const float* __restrict__ in,
                         bf16* __restrict__ oh, bf16* __restrict__ ol) {
    long i = ((long)blockIdx.x * 256 + threadIdx.x) * 4;
    float4 v = *(const float4*)(in + i);
    float h0 = __bfloat162float(__float2bfloat16(v.x));
    float h1 = __bfloat162float(__float2bfloat16(v.y));
    float h2 = __bfloat162float(__float2bfloat16(v.z));
    float h3 = __bfloat162float(__float2bfloat16(v.w));
    *(__nv_bfloat162*)(oh + i)     = __floats2bfloat162_rn(h0, h1);
    *(__nv_bfloat162*)(oh + i + 2) = __floats2bfloat162_rn(h2, h3);
    *(__nv_bfloat162*)(ol + i)     = __floats2bfloat162_rn(v.x - h0, v.y - h1);
    *(__nv_bfloat162*)(ol + i + 2) = __floats2bfloat162_rn(v.z - h2, v.w - h3);
}

// transpose + split: in[inst][R][C] fp32  ->  oh/ol[inst][C][R] bf16
__global__ void transcvt(const float* __restrict__ in,
                         bf16* __restrict__ oh, bf16* __restrict__ ol,
                         int R, int C) {
    __shared__ float t[32][33];
    long base = (long)blockIdx.z * R * C;
    int r0 = blockIdx.y * 32, c0 = blockIdx.x * 32;
    int tx = threadIdx.x, ty = threadIdx.y;
    #pragma unroll
    for (int j = ty; j < 32; j += 8)
        t[j][tx] = in[base + (long)(r0 + j) * C + c0 + tx];
    __syncthreads();
    #pragma unroll
    for (int j = ty; j < 32; j += 8) {
        float v = t[tx][j];
        float h = __bfloat162float(__float2bfloat16(v));
        long o = base + (long)(c0 + j) * R + r0 + tx;
        oh[o] = __float2bfloat16(h);
        ol[o] = __float2bfloat16(v - h);
    }
}

// ---------------- bf16x3 GEMM on mma.sync ------------------------------------
// C[m][n] = sum_k A[m][k]*Wt[n][k];  A = ah+al, Wt = bh+bl (3-product scheme).
// CTA tile 128x128, K-chunk 32, 8 warps (4 m x 2 n), warp tile 32x64.
#define KC    32
#define SSTR  40                       // 32 + 8 pad (bf16 units)
#define TILE_E (128 * SSTR)            // 5120 bf16 per operand tile
#define STAGE_E (4 * TILE_E)           // 20480 bf16 per stage
#define GSMEM (2 * STAGE_E * 2)        // bytes: 81920

__global__ __launch_bounds__(256, 1)
void gemm_mma(const bf16* __restrict__ Ah, const bf16* __restrict__ Al,
              const bf16* __restrict__ Bh0, const bf16* __restrict__ Bl0,
              float* __restrict__ C0, int ldc, long bstride, long cstride)
{
    extern __shared__ __align__(16) bf16 sh[];
    const int tid  = threadIdx.x;
    const int lane = tid & 31;
    const int wid  = tid >> 5;
    const int wm   = wid & 3;            // warp m index (32 rows each)
    const int wn   = wid >> 2;           // warp n index (64 cols each)
    const int m0   = blockIdx.y * 128;
    const int n0   = blockIdx.x * 128;

    const bf16* Bh = Bh0 + (long)blockIdx.z * bstride;
    const bf16* Bl = Bl0 + (long)blockIdx.z * bstride;
    float* C = C0 + (long)blockIdx.z * cstride;

    // global load slots: 512 uint4 per tile; this thread handles slots tid, tid+256
    const int ra = tid >> 2;             // row 0..63 (and +64)
    const int ca = (tid & 3) * 8;        // bf16 col offset within 32
    const long gA = (long)(m0 + ra) * DD + ca;
    const long gB = (long)(n0 + ra) * DD + ca;
    const int  so = ra * SSTR + ca;

    // ldmatrix base offsets (bf16 units, within a stage)
    uint32_t sbase = (uint32_t)__cvta_generic_to_shared(sh);
    int offA[2], offB[4];
    #pragma unroll
    for (int mf = 0; mf < 2; mf++)
        offA[mf] = (wm * 32 + mf * 16 + (lane & 15)) * SSTR + ((lane >> 4) * 8);
    #pragma unroll
    for (int nfp = 0; nfp < 4; nfp++)
        offB[nfp] = (wn * 64 + nfp * 16 + (lane & 7) + ((lane & 16) >> 1)) * SSTR
                  + ((lane & 8) ? 8 : 0);

    float acc[2][8][4];
    #pragma unroll
    for (int mf = 0; mf < 2; mf++)
        #pragma unroll
        for (int nf = 0; nf < 8; nf++)
            #pragma unroll
            for (int c = 0; c < 4; c++) acc[mf][nf][c] = 0.f;

    uint4 pAh[2], pAl[2], pBh[2], pBl[2];
    // prefetch chunk 0
    pAh[0] = *(const uint4*)(Ah + gA);  pAh[1] = *(const uint4*)(Ah + gA + 64 * DD);
    pAl[0] = *(const uint4*)(Al + gA);  pAl[1] = *(const uint4*)(Al + gA + 64 * DD);
    pBh[0] = *(const uint4*)(Bh + gB);  pBh[1] = *(const uint4*)(Bh + gB + 64 * DD);
    pBl[0] = *(const uint4*)(Bl + gB);  pBl[1] = *(const uint4*)(Bl + gB + 64 * DD);

    #pragma unroll 1
    for (int i = 0; i < DD / KC; i++) {
        const int st = i & 1;
        bf16* s = sh + st * STAGE_E;
        *(uint4*)(s + so)                        = pAh[0];
        *(uint4*)(s + so + 64 * SSTR)            = pAh[1];
        *(uint4*)(s + TILE_E + so)               = pAl[0];
        *(uint4*)(s + TILE_E + so + 64 * SSTR)   = pAl[1];
        *(uint4*)(s + 2*TILE_E + so)             = pBh[0];
        *(uint4*)(s + 2*TILE_E + so + 64 * SSTR) = pBh[1];
        *(uint4*)(s + 3*TILE_E + so)             = pBl[0];
        *(uint4*)(s + 3*TILE_E + so + 64 * SSTR) = pBl[1];
        __syncthreads();

        if (i + 1 < DD / KC) {
            const long kn = (long)(i + 1) * KC;
            pAh[0] = *(const uint4*)(Ah + gA + kn);  pAh[1] = *(const uint4*)(Ah + gA + kn + 64 * DD);
            pAl[0] = *(const uint4*)(Al + gA + kn);  pAl[1] = *(const uint4*)(Al + gA + kn + 64 * DD);
            pBh[0] = *(const uint4*)(Bh + gB + kn);  pBh[1] = *(const uint4*)(Bh + gB + kn + 64 * DD);
            pBl[0] = *(const uint4*)(Bl + gB + kn);  pBl[1] = *(const uint4*)(Bl + gB + kn + 64 * DD);
        }

        const uint32_t stb = sbase + st * (STAGE_E * 2);   // bytes
        #pragma unroll
        for (int ks = 0; ks < 2; ks++) {
            const int kb = ks * 16;                         // bf16 offset
            uint32_t fah[2][4], fal[2][4], fbh[4][4], fbl[4][4];
            #pragma unroll
            for (int mf = 0; mf < 2; mf++) {
                LDSM4(fah[mf], stb + (offA[mf] + kb) * 2);
                LDSM4(fal[mf], stb + (TILE_E + offA[mf] + kb) * 2);
            }
            #pragma unroll
            for (int nfp = 0; nfp < 4; nfp++) {
                LDSM4(fbh[nfp], stb + (2*TILE_E + offB[nfp] + kb) * 2);
                LDSM4(fbl[nfp], stb + (3*TILE_E + offB[nfp] + kb) * 2);
            }
            #pragma unroll
            for (int mf = 0; mf < 2; mf++)
                #pragma unroll
                for (int nf = 0; nf < 8; nf++) {
                    const int g = nf >> 1, p = (nf & 1) * 2;
                    MMA16816(acc[mf][nf], fah[mf], fbh[g][p], fbh[g][p + 1]);
                    MMA16816(acc[mf][nf], fah[mf], fbl[g][p], fbl[g][p + 1]);
                    MMA16816(acc[mf][nf], fal[mf], fbh[g][p], fbh[g][p + 1]);
                }
        }
        __syncthreads();
    }

    // epilogue
    #pragma unroll
    for (int mf = 0; mf < 2; mf++) {
        const int row = m0 + wm * 32 + mf * 16 + (lane >> 2);
        #pragma unroll
        for (int nf = 0; nf < 8; nf++) {
            const int col = n0 + wn * 64 + nf * 8 + (lane & 3) * 2;
            float* Cp = C + (long)row * ldc + col;
            *(float2*)Cp              = make_float2(acc[mf][nf][0], acc[mf][nf][1]);
            *(float2*)(Cp + 8 * ldc)  = make_float2(acc[mf][nf][2], acc[mf][nf][3]);
        }
    }
}

// ---------------- RMSNorm + RoPE + q scale (in place) ------------------------
__global__ void normrope_kernel(float* __restrict__ gq, float* __restrict__ gk,
                                const int* __restrict__ positions,
                                const float* __restrict__ qns,
                                const float* __restrict__ kns)
{
    const int m    = blockIdx.x;
    const int head = blockIdx.y;
    float* buf; const float* nsc; float omult;
    if (head < NQ) { buf = gq + ((long)head * MT + m) * HH;        nsc = qns; omult = 0.0625f; }
    else           { buf = gk + ((long)(head - NQ) * MT + m) * HH; nsc = kns; omult = 1.0f; }

    const int t = threadIdx.x;   // 64 threads
    __shared__ float row[256];
    __shared__ float red[2];

    float4 v = *(const float4*)&buf[t * 4];
    float ss = v.x * v.x + v.y * v.y + v.z * v.z + v.w * v.w;
    #pragma unroll
    for (int o = 16; o > 0; o >>= 1) ss += __shfl_xor_sync(0xffffffffu, ss, o);
    if ((t & 31) == 0) red[t >> 5] = ss;
    __syncthreads();
    float r = rsqrtf((red[0] + red[1]) * (1.0f / 256.0f) + 1e-6f);

    float4 sc = *(const float4*)&nsc[t * 4];
    row[t * 4 + 0] = v.x * r * (1.0f + sc.x);
    row[t * 4 + 1] = v.y * r * (1.0f + sc.y);
    row[t * 4 + 2] = v.z * r * (1.0f + sc.z);
    row[t * 4 + 3] = v.w * r * (1.0f + sc.w);
    __syncthreads();

    if (t < 32) {
        float pos = (float)positions[m];
        #pragma unroll
        for (int c = 0; c < 4; c++) {
            int h = t * 4 + c;                          // 0..127
            float ts = powf(10000.0f, (float)h * (1.0f / 128.0f));
            float ang = pos / ts;
            float sn, cs;
            sincosf(ang, &sn, &cs);
            float f = row[h], s = row[h + 128];
            buf[h]       = (f * cs - s * sn) * omult;
            buf[h + 128] = (s * cs + f * sn) * omult;
        }
    }
}

// ---------------- flash attention, sliding window 1024 -----------------------
#define BQ    64
#define QSTR  260
#define KSTR  260
#define VSTR  260
#define PSTR  33
#define ATTN_SMEM (((BQ + 32 + 32) * 260 + BQ * PSTR) * 4)

__device__ __forceinline__ float redmax16(float v) {
    #pragma unroll
    for (int o = 8; o > 0; o >>= 1) v = fmaxf(v, __shfl_xor_sync(0xffffffffu, v, o));
    return v;
}
__device__ __forceinline__ float redsum16(float v) {
    #pragma unroll
    for (int o = 8; o > 0; o >>= 1) v += __shfl_xor_sync(0xffffffffu, v, o);
    return v;
}

__global__ __launch_bounds__(256, 1)
void attn_kernel(const float* __restrict__ qb, const float* __restrict__ kb,
                 const float* __restrict__ vb, float* __restrict__ ob)
{
    extern __shared__ __align__(16) float sm[];
    float* Qs = sm;                  // [64][260]
    float* Ks = Qs + BQ * QSTR;      // [32][260]
    float* Vs = Ks + 32 * KSTR;      // [32][260]
    float* Ps = Vs + 32 * VSTR;      // [64][33]

    const int tid = threadIdx.x;
    const int tx  = tid & 15;
    const int ty  = tid >> 4;
    const int t0  = blockIdx.x * BQ;
    const int n   = blockIdx.y;
    const int b   = blockIdx.z;
    const int kvh = n >> 1;

    const float* qptr = qb + ((long)n   * MT + b * TSEQ + t0) * HH;
    const float* kptr = kb + ((long)kvh * MT + b * TSEQ)      * HH;
    const float* vptr = vb + ((long)kvh * MT + b * TSEQ)      * HH;

    for (int e = tid * 4; e < BQ * HH; e += 1024) {
        int q = e >> 8, d = e & 255;
        *(float4*)&Qs[q * QSTR + d] = *(const float4*)&qptr[q * HH + d];
    }

    const int q0 = ty * 4;
    float mrow[4] = {-1e30f, -1e30f, -1e30f, -1e30f};
    float lrow[4] = {0.f, 0.f, 0.f, 0.f};
    ull O2[4][8];
    #pragma unroll
    for (int i = 0; i < 4; i++)
        #pragma unroll
        for (int p = 0; p < 8; p++) O2[i][p] = 0ull;

    int s_begin = t0 - (WIN - 1); if (s_begin < 0) s_begin = 0;
    s_begin &= ~31;
    const int s_end = t0 + BQ - 1;

    for (int s0 = s_begin; s0 <= s_end; s0 += 32) {
        __syncthreads();
        for (int e = tid * 4; e < 32 * HH; e += 1024) {
            int j = e >> 8, d = e & 255;
            *(float4*)&Ks[j * KSTR + d] = *(const float4*)&kptr[(long)(s0 + j) * HH + d];
            *(float4*)&Vs[j * VSTR + d] = *(const float4*)&vptr[(long)(s0 + j) * HH + d];
        }
        __syncthreads();

        ull S2[4][2];
        #pragma unroll
        for (int i = 0; i < 4; i++) { S2[i][0] = 0ull; S2[i][1] = 0ull; }
        #pragma unroll 4
        for (int d2 = 0; d2 < 128; d2++) {
            ull kp0 = *(const ull*)&Ks[tx * KSTR + 2 * d2];
            ull kp1 = *(const ull*)&Ks[(tx + 16) * KSTR + 2 * d2];
            #pragma unroll
            for (int i = 0; i < 4; i++) {
                ull qp = *(const ull*)&Qs[(q0 + i) * QSTR + 2 * d2];
                ffma2(S2[i][0], qp, kp0);
                ffma2(S2[i][1], qp, kp1);
            }
        }

        float fac[4];
        #pragma unroll
        for (int i = 0; i < 4; i++) {
            float2 f0 = upk2(S2[i][0]);
            float2 f1 = upk2(S2[i][1]);
            float sv0 = f0.x + f0.y;
            float sv1 = f1.x + f1.y;
            int t = t0 + q0 + i;
            int sA = s0 + tx, sB = s0 + tx + 16;
            bool v0 = (sA <= t) && (sA > t - WIN);
            bool v1 = (sB <= t) && (sB > t - WIN);
            if (!v0) sv0 = -1e30f;
            if (!v1) sv1 = -1e30f;

            float mx = redmax16(fmaxf(sv0, sv1));
            float mn = fmaxf(mrow[i], mx);
            fac[i] = __expf(mrow[i] - mn);
            mrow[i] = mn;
            float p0 = v0 ? __expf(sv0 - mn) : 0.f;
            float p1 = v1 ? __expf(sv1 - mn) : 0.f;
            Ps[(q0 + i) * PSTR + tx]      = p0;
            Ps[(q0 + i) * PSTR + tx + 16] = p1;
            lrow[i] = lrow[i] * fac[i] + redsum16(p0 + p1);
        }
        __syncwarp();

        #pragma unroll
        for (int i = 0; i < 4; i++) {
            ull f = pk2(fac[i], fac[i]);
            #pragma unroll
            for (int p = 0; p < 8; p++) O2[i][p] = mul2(O2[i][p], f);
        }

        #pragma unroll 4
        for (int j = 0; j < 32; j++) {
            int jj = (j + tx) & 31;
            const ull* vrow = (const ull*)&Vs[jj * VSTR + tx * 16];
            ull pp[4];
            #pragma unroll
            for (int i = 0; i < 4; i++) {
                float pv = Ps[(q0 + i) * PSTR + jj];
                pp[i] = pk2(pv, pv);
            }
            #pragma unroll
            for (int p = 0; p < 8; p++) {
                ull vv = vrow[p];
                #pragma unroll
                for (int i = 0; i < 4; i++) ffma2(O2[i][p], pp[i], vv);
            }
        }
    }

    #pragma unroll
    for (int i = 0; i < 4; i++) {
        float inv = 1.0f / lrow[i];
        ull s = pk2(inv, inv);
        long m = (long)b * TSEQ + t0 + q0 + i;
        #pragma unroll
        for (int p = 0; p < 8; p++) {
            float2 o = upk2(mul2(O2[i][p], s));
            *(float2*)&ob[m * DD + n * HH + tx * 16 + 2 * p] = o;
        }
    }
}

// ---------------- launcher ---------------------------------------------------
extern "C" void kernel_launch(void* const* d_in, const int* in_sizes, int n_in,
                              void* d_out, int out_size) {
    const float* x    = (const float*)d_in[0];
    const int*   pos  = (const int*)  d_in[1];
    const float* q_w  = (const float*)d_in[2];
    const float* k_w  = (const float*)d_in[3];
    const float* v_w  = (const float*)d_in[4];
    const float* o_w  = (const float*)d_in[5];
    const float* qns  = (const float*)d_in[6];
    const float* kns  = (const float*)d_in[7];
    float* out = (float*)d_out;

    float *pq, *pk, *pv, *patt;
    bf16 *pxh, *pxl, *pah, *pal;
    bf16 *pwqh, *pwql, *pwkh, *pwkl, *pwvh, *pwvl, *pwoh, *pwol;
    cudaGetSymbolAddress((void**)&pq,   g_q);
    cudaGetSymbolAddress((void**)&pk,   g_k);
    cudaGetSymbolAddress((void**)&pv,   g_v);
    cudaGetSymbolAddress((void**)&patt, g_att);
    cudaGetSymbolAddress((void**)&pxh,  g_xh);
    cudaGetSymbolAddress((void**)&pxl,  g_xl);
    cudaGetSymbolAddress((void**)&pah,  g_ah);
    cudaGetSymbolAddress((void**)&pal,  g_al);
    cudaGetSymbolAddress((void**)&pwqh, g_wqh);
    cudaGetSymbolAddress((void**)&pwql, g_wql);
    cudaGetSymbolAddress((void**)&pwkh, g_wkh);
    cudaGetSymbolAddress((void**)&pwkl, g_wkl);
    cudaGetSymbolAddress((void**)&pwvh, g_wvh);
    cudaGetSymbolAddress((void**)&pwvl, g_wvl);
    cudaGetSymbolAddress((void**)&pwoh, g_woh);
    cudaGetSymbolAddress((void**)&pwol, g_wol);

    cudaFuncSetAttribute(attn_kernel,
                         cudaFuncAttributeMaxDynamicSharedMemorySize, ATTN_SMEM);
    cudaFuncSetAttribute(gemm_mma,
                         cudaFuncAttributeMaxDynamicSharedMemorySize, GSMEM);

    // split x and weights into bf16 hi/lo (weights also K-major transposed)
    cvt_hilo<<<(MT * DD) / 1024, 256>>>(x, pxh, pxl);
    transcvt<<<dim3(HH / 32, DD / 32, NQ),  dim3(32, 8)>>>(q_w, pwqh, pwql, DD, HH);
    transcvt<<<dim3(HH / 32, DD / 32, NKV), dim3(32, 8)>>>(k_w, pwkh, pwkl, DD, HH);
    transcvt<<<dim3(HH / 32, DD / 32, NKV), dim3(32, 8)>>>(v_w, pwvh, pwvl, DD, HH);
    transcvt<<<dim3(DD / 32, DD / 32, 1),   dim3(32, 8)>>>(o_w, pwoh, pwol, DD, DD);

    // Q/K/V projections on tensor cores (bf16x3, mma.sync)
    gemm_mma<<<dim3(2, 32, NQ),  256, GSMEM>>>(pxh, pxl, pwqh, pwql, pq, HH,
                                               (long)HH * DD, (long)MT * HH);
    gemm_mma<<<dim3(2, 32, NKV), 256, GSMEM>>>(pxh, pxl, pwkh, pwkl, pk, HH,
                                               (long)HH * DD, (long)MT * HH);
    gemm_mma<<<dim3(2, 32, NKV), 256, GSMEM>>>(pxh, pxl, pwvh, pwvl, pv, HH,
                                               (long)HH * DD, (long)MT * HH);

    // RMSNorm + RoPE (+ q * H^-0.5)
    normrope_kernel<<<dim3(MT, NQ + NKV), 64>>>(pq, pk, pos, qns, kns);

    // windowed attention -> g_att [m][n*H+h]
    attn_kernel<<<dim3(TSEQ / BQ, NQ, 2), 256, ATTN_SMEM>>>(pq, pk, pv, patt);

    // output projection on tensor cores
    cvt_hilo<<<(MT * DD) / 1024, 256>>>(patt, pah, pal);
    gemm_mma<<<dim3(16, 32, 1), 256, GSMEM>>>(pah, pal, pwoh, pwol, out, DD, 0, 0);
}

// round 17
// speedup vs baseline: 2.0364x; 1.3638x over previous
#include <cuda_runtime.h>
#include <cuda_bf16.h>
#include <cstdint>

typedef unsigned long long ull;
typedef __nv_bfloat16 bf16;

#define MT   4096
#define DD   2048
#define HH   256
#define NQ   8
#define NKV  4
#define TSEQ 2048
#define WIN  1024

// ---------------- static device scratch (no allocations) --------------------
__device__ __align__(256) float g_q[(size_t)NQ  * MT * HH];
__device__ __align__(256) float g_k[(size_t)NKV * MT * HH];
__device__ __align__(256) float g_v[(size_t)NKV * MT * HH];
// bf16 hi/lo split operands
__device__ __align__(256) bf16 g_xh[(size_t)MT * DD];
__device__ __align__(256) bf16 g_xl[(size_t)MT * DD];
__device__ __align__(256) bf16 g_ah[(size_t)MT * DD];    // attention out hi
__device__ __align__(256) bf16 g_al[(size_t)MT * DD];    // attention out lo
// q/k/v hi-lo bf16 (post norm+rope)
__device__ __align__(256) bf16 g_qbh[(size_t)NQ  * MT * HH];
__device__ __align__(256) bf16 g_qbl[(size_t)NQ  * MT * HH];
__device__ __align__(256) bf16 g_kbh[(size_t)NKV * MT * HH];
__device__ __align__(256) bf16 g_kbl[(size_t)NKV * MT * HH];
__device__ __align__(256) bf16 g_vbh[(size_t)NKV * MT * HH];
__device__ __align__(256) bf16 g_vbl[(size_t)NKV * MT * HH];
// transposed weights: Wt[n][k] (row = output index, K-major)
__device__ __align__(256) bf16 g_wqh[(size_t)NQ  * HH * DD];
__device__ __align__(256) bf16 g_wql[(size_t)NQ  * HH * DD];
__device__ __align__(256) bf16 g_wkh[(size_t)NKV * HH * DD];
__device__ __align__(256) bf16 g_wkl[(size_t)NKV * HH * DD];
__device__ __align__(256) bf16 g_wvh[(size_t)NKV * HH * DD];
__device__ __align__(256) bf16 g_wvl[(size_t)NKV * HH * DD];
__device__ __align__(256) bf16 g_woh[(size_t)DD * DD];
__device__ __align__(256) bf16 g_wol[(size_t)DD * DD];

// ---------------- mma.sync / ldmatrix helpers --------------------------------
#define LDSM4(r, a) \
    asm volatile("ldmatrix.sync.aligned.m8n8.x4.shared.b16 {%0,%1,%2,%3}, [%4];" \
        : "=r"((r)[0]), "=r"((r)[1]), "=r"((r)[2]), "=r"((r)[3]) : "r"(a))

#define LDSM4T(r, a) \
    asm volatile("ldmatrix.sync.aligned.m8n8.x4.trans.shared.b16 {%0,%1,%2,%3}, [%4];" \
        : "=r"((r)[0]), "=r"((r)[1]), "=r"((r)[2]), "=r"((r)[3]) : "r"(a))

#define MMA16816(c, a, b0, b1) \
    asm volatile("mma.sync.aligned.m16n8k16.row.col.f32.bf16.bf16.f32 " \
        "{%0,%1,%2,%3}, {%4,%5,%6,%7}, {%8,%9}, {%0,%1,%2,%3};" \
        : "+f"((c)[0]), "+f"((c)[1]), "+f"((c)[2]), "+f"((c)[3]) \
        : "r"((a)[0]), "r"((a)[1]), "r"((a)[2]), "r"((a)[3]), "r"(b0), "r"(b1))

__device__ __forceinline__ uint32_t bf16x2_of(float lo, float hi) {
    __nv_bfloat162 t = __floats2bfloat162_rn(lo, hi);   // x = lo (low half)
    return *(uint32_t*)&t;
}

// ---------------- conversion kernels -----------------------------------------
__global__ void cvt_hilo(const float* __restrict__ in,
                         bf16* __restrict__ oh, bf16* __restrict__ ol) {
    long i = ((long)blockIdx.x * 256 + threadIdx.x) * 4;
    float4 v = *(const float4*)(in + i);
    float h0 = __bfloat162float(__float2bfloat16(v.x));
    float h1 = __bfloat162float(__float2bfloat16(v.y));
    float h2 = __bfloat162float(__float2bfloat16(v.z));
    float h3 = __bfloat162float(__float2bfloat16(v.w));
    *(__nv_bfloat162*)(oh + i)     = __floats2bfloat162_rn(h0, h1);
    *(__nv_bfloat162*)(oh + i + 2) = __floats2bfloat162_rn(h2, h3);
    *(__nv_bfloat162*)(ol + i)     = __floats2bfloat162_rn(v.x - h0, v.y - h1);
    *(__nv_bfloat162*)(ol + i + 2) = __floats2bfloat162_rn(v.z - h2, v.w - h3);
}

// transpose + split: in[inst][R][C] fp32  ->  oh/ol[inst][C][R] bf16
__global__ void transcvt(const float* __restrict__ in,
                         bf16* __restrict__ oh, bf16* __restrict__ ol,
                         int R, int C) {
    __shared__ float t[32][33];
    long base = (long)blockIdx.z * R * C;
    int r0 = blockIdx.y * 32, c0 = blockIdx.x * 32;
    int tx = threadIdx.x, ty = threadIdx.y;
    #pragma unroll
    for (int j = ty; j < 32; j += 8)
        t[j][tx] = in[base + (long)(r0 + j) * C + c0 + tx];
    __syncthreads();
    #pragma unroll
    for (int j = ty; j < 32; j += 8) {
        float v = t[tx][j];
        float h = __bfloat162float(__float2bfloat16(v));
        long o = base + (long)(c0 + j) * R + r0 + tx;
        oh[o] = __float2bfloat16(h);
        ol[o] = __float2bfloat16(v - h);
    }
}

// ---------------- bf16x3 GEMM on mma.sync (unchanged from R16) ---------------
#define KC    32
#define SSTR  40
#define TILE_E (128 * SSTR)
#define STAGE_E (4 * TILE_E)
#define GSMEM (2 * STAGE_E * 2)

__global__ __launch_bounds__(256, 1)
void gemm_mma(const bf16* __restrict__ Ah, const bf16* __restrict__ Al,
              const bf16* __restrict__ Bh0, const bf16* __restrict__ Bl0,
              float* __restrict__ C0, int ldc, long bstride, long cstride)
{
    extern __shared__ __align__(16) bf16 sh[];
    const int tid  = threadIdx.x;
    const int lane = tid & 31;
    const int wid  = tid >> 5;
    const int wm   = wid & 3;
    const int wn   = wid >> 2;
    const int m0   = blockIdx.y * 128;
    const int n0   = blockIdx.x * 128;

    const bf16* Bh = Bh0 + (long)blockIdx.z * bstride;
    const bf16* Bl = Bl0 + (long)blockIdx.z * bstride;
    float* C = C0 + (long)blockIdx.z * cstride;

    const int ra = tid >> 2;
    const int ca = (tid & 3) * 8;
    const long gA = (long)(m0 + ra) * DD + ca;
    const long gB = (long)(n0 + ra) * DD + ca;
    const int  so = ra * SSTR + ca;

    uint32_t sbase = (uint32_t)__cvta_generic_to_shared(sh);
    int offA[2], offB[4];
    #pragma unroll
    for (int mf = 0; mf < 2; mf++)
        offA[mf] = (wm * 32 + mf * 16 + (lane & 15)) * SSTR + ((lane >> 4) * 8);
    #pragma unroll
    for (int nfp = 0; nfp < 4; nfp++)
        offB[nfp] = (wn * 64 + nfp * 16 + (lane & 7) + ((lane & 16) >> 1)) * SSTR
                  + ((lane & 8) ? 8 : 0);

    float acc[2][8][4];
    #pragma unroll
    for (int mf = 0; mf < 2; mf++)
        #pragma unroll
        for (int nf = 0; nf < 8; nf++)
            #pragma unroll
            for (int c = 0; c < 4; c++) acc[mf][nf][c] = 0.f;

    uint4 pAh[2], pAl[2], pBh[2], pBl[2];
    pAh[0] = *(const uint4*)(Ah + gA);  pAh[1] = *(const uint4*)(Ah + gA + 64 * DD);
    pAl[0] = *(const uint4*)(Al + gA);  pAl[1] = *(const uint4*)(Al + gA + 64 * DD);
    pBh[0] = *(const uint4*)(Bh + gB);  pBh[1] = *(const uint4*)(Bh + gB + 64 * DD);
    pBl[0] = *(const uint4*)(Bl + gB);  pBl[1] = *(const uint4*)(Bl + gB + 64 * DD);

    #pragma unroll 1
    for (int i = 0; i < DD / KC; i++) {
        const int st = i & 1;
        bf16* s = sh + st * STAGE_E;
        *(uint4*)(s + so)                        = pAh[0];
        *(uint4*)(s + so + 64 * SSTR)            = pAh[1];
        *(uint4*)(s + TILE_E + so)               = pAl[0];
        *(uint4*)(s + TILE_E + so + 64 * SSTR)   = pAl[1];
        *(uint4*)(s + 2*TILE_E + so)             = pBh[0];
        *(uint4*)(s + 2*TILE_E + so + 64 * SSTR) = pBh[1];
        *(uint4*)(s + 3*TILE_E + so)             = pBl[0];
        *(uint4*)(s + 3*TILE_E + so + 64 * SSTR) = pBl[1];
        __syncthreads();

        if (i + 1 < DD / KC) {
            const long kn = (long)(i + 1) * KC;
            pAh[0] = *(const uint4*)(Ah + gA + kn);  pAh[1] = *(const uint4*)(Ah + gA + kn + 64 * DD);
            pAl[0] = *(const uint4*)(Al + gA + kn);  pAl[1] = *(const uint4*)(Al + gA + kn + 64 * DD);
            pBh[0] = *(const uint4*)(Bh + gB + kn);  pBh[1] = *(const uint4*)(Bh + gB + kn + 64 * DD);
            pBl[0] = *(const uint4*)(Bl + gB + kn);  pBl[1] = *(const uint4*)(Bl + gB + kn + 64 * DD);
        }

        const uint32_t stb = sbase + st * (STAGE_E * 2);
        #pragma unroll
        for (int ks = 0; ks < 2; ks++) {
            const int kb = ks * 16;
            uint32_t fah[2][4], fal[2][4], fbh[4][4], fbl[4][4];
            #pragma unroll
            for (int mf = 0; mf < 2; mf++) {
                LDSM4(fah[mf], stb + (offA[mf] + kb) * 2);
                LDSM4(fal[mf], stb + (TILE_E + offA[mf] + kb) * 2);
            }
            #pragma unroll
            for (int nfp = 0; nfp < 4; nfp++) {
                LDSM4(fbh[nfp], stb + (2*TILE_E + offB[nfp] + kb) * 2);
                LDSM4(fbl[nfp], stb + (3*TILE_E + offB[nfp] + kb) * 2);
            }
            #pragma unroll
            for (int mf = 0; mf < 2; mf++)
                #pragma unroll
                for (int nf = 0; nf < 8; nf++) {
                    const int g = nf >> 1, p = (nf & 1) * 2;
                    MMA16816(acc[mf][nf], fah[mf], fbh[g][p], fbh[g][p + 1]);
                    MMA16816(acc[mf][nf], fah[mf], fbl[g][p], fbl[g][p + 1]);
                    MMA16816(acc[mf][nf], fal[mf], fbh[g][p], fbh[g][p + 1]);
                }
        }
        __syncthreads();
    }

    #pragma unroll
    for (int mf = 0; mf < 2; mf++) {
        const int row = m0 + wm * 32 + mf * 16 + (lane >> 2);
        #pragma unroll
        for (int nf = 0; nf < 8; nf++) {
            const int col = n0 + wn * 64 + nf * 8 + (lane & 3) * 2;
            float* Cp = C + (long)row * ldc + col;
            *(float2*)Cp              = make_float2(acc[mf][nf][0], acc[mf][nf][1]);
            *(float2*)(Cp + 8 * ldc)  = make_float2(acc[mf][nf][2], acc[mf][nf][3]);
        }
    }
}

// ---------------- RMSNorm + RoPE + q scale -> bf16 hi/lo ---------------------
__global__ void normrope_kernel(const float* __restrict__ gq, const float* __restrict__ gk,
                                bf16* __restrict__ qbh, bf16* __restrict__ qbl,
                                bf16* __restrict__ kbh, bf16* __restrict__ kbl,
                                const int* __restrict__ positions,
                                const float* __restrict__ qns,
                                const float* __restrict__ kns)
{
    const int m    = blockIdx.x;
    const int head = blockIdx.y;
    const float* buf; bf16 *oh, *ol; const float* nsc; float omult;
    if (head < NQ) {
        long off = ((long)head * MT + m) * HH;
        buf = gq + off; oh = qbh + off; ol = qbl + off; nsc = qns; omult = 0.0625f;
    } else {
        long off = ((long)(head - NQ) * MT + m) * HH;
        buf = gk + off; oh = kbh + off; ol = kbl + off; nsc = kns; omult = 1.0f;
    }

    const int t = threadIdx.x;   // 64 threads
    __shared__ float row[256];
    __shared__ float outv[256];
    __shared__ float red[2];

    float4 v = *(const float4*)&buf[t * 4];
    float ss = v.x * v.x + v.y * v.y + v.z * v.z + v.w * v.w;
    #pragma unroll
    for (int o = 16; o > 0; o >>= 1) ss += __shfl_xor_sync(0xffffffffu, ss, o);
    if ((t & 31) == 0) red[t >> 5] = ss;
    __syncthreads();
    float r = rsqrtf((red[0] + red[1]) * (1.0f / 256.0f) + 1e-6f);

    float4 sc = *(const float4*)&nsc[t * 4];
    row[t * 4 + 0] = v.x * r * (1.0f + sc.x);
    row[t * 4 + 1] = v.y * r * (1.0f + sc.y);
    row[t * 4 + 2] = v.z * r * (1.0f + sc.z);
    row[t * 4 + 3] = v.w * r * (1.0f + sc.w);
    __syncthreads();

    if (t < 32) {
        float pos = (float)positions[m];
        #pragma unroll
        for (int c = 0; c < 4; c++) {
            int h = t * 4 + c;                          // 0..127
            float ts = powf(10000.0f, (float)h * (1.0f / 128.0f));
            float ang = pos / ts;
            float sn, cs;
            sincosf(ang, &sn, &cs);
            float f = row[h], s = row[h + 128];
            outv[h]       = (f * cs - s * sn) * omult;
            outv[h + 128] = (s * cs + f * sn) * omult;
        }
    }
    __syncthreads();

    // all 64 threads: hi/lo split + store (4 elems each = 2 bf16x2 pairs)
    #pragma unroll
    for (int p = 0; p < 2; p++) {
        int h = t * 4 + p * 2;
        float a = outv[h], bv = outv[h + 1];
        float ha = __bfloat162float(__float2bfloat16(a));
        float hb = __bfloat162float(__float2bfloat16(bv));
        *(uint32_t*)&oh[h] = bf16x2_of(ha, hb);
        *(uint32_t*)&ol[h] = bf16x2_of(a - ha, bv - hb);
    }
}

// ---------------- flash attention on mma.sync (bf16x3) -----------------------
#define BQ    64
#define KT    64
#define DSTR  264
#define ATILE (64 * DSTR)
#define ATTN_SMEM (6 * ATILE * 2)

__global__ __launch_bounds__(128, 1)
void attn_mma(const bf16* __restrict__ qh, const bf16* __restrict__ ql,
              const bf16* __restrict__ kh, const bf16* __restrict__ kl,
              const bf16* __restrict__ vh, const bf16* __restrict__ vl,
              bf16* __restrict__ ohp, bf16* __restrict__ olp)
{
    extern __shared__ __align__(16) bf16 sh2[];
    bf16* Qh = sh2;
    bf16* Ql = Qh + ATILE;
    bf16* Kh = Ql + ATILE;
    bf16* Kl = Kh + ATILE;
    bf16* Vh = Kl + ATILE;
    bf16* Vl = Vh + ATILE;

    const int tid  = threadIdx.x;
    const int lane = tid & 31;
    const int w    = tid >> 5;            // 4 warps, warp owns rows [16w,16w+16)
    const int t0   = blockIdx.x * BQ;
    const int n    = blockIdx.y;
    const int b    = blockIdx.z;
    const int kvh  = n >> 1;

    const bf16* qhg = qh + ((long)n   * MT + b * TSEQ + t0) * HH;
    const bf16* qlg = ql + ((long)n   * MT + b * TSEQ + t0) * HH;
    const bf16* khg = kh + ((long)kvh * MT + b * TSEQ) * HH;
    const bf16* klg = kl + ((long)kvh * MT + b * TSEQ) * HH;
    const bf16* vhg = vh + ((long)kvh * MT + b * TSEQ) * HH;
    const bf16* vlg = vl + ((long)kvh * MT + b * TSEQ) * HH;

    // Q tile (resident)
    for (int e = tid; e < 2048; e += 128) {
        int r = e >> 5, c = (e & 31) * 8;
        *(uint4*)&Qh[r * DSTR + c] = *(const uint4*)&qhg[(long)r * HH + c];
        *(uint4*)&Ql[r * DSTR + c] = *(const uint4*)&qlg[(long)r * HH + c];
    }

    const uint32_t sB  = (uint32_t)__cvta_generic_to_shared(sh2);
    const uint32_t QhB = sB;
    const uint32_t QlB = sB + 1 * ATILE * 2;
    const uint32_t KhB = sB + 2 * ATILE * 2;
    const uint32_t KlB = sB + 3 * ATILE * 2;
    const uint32_t VhB = sB + 4 * ATILE * 2;
    const uint32_t VlB = sB + 5 * ATILE * 2;

    const int offQ = (16 * w + (lane & 15)) * DSTR + (lane >> 4) * 8;
    int offK[4];
    #pragma unroll
    for (int nb = 0; nb < 4; nb++)
        offK[nb] = (nb * 16 + (lane & 7) + 8 * (lane >> 4)) * DSTR + ((lane & 8) ? 8 : 0);
    const int offVr = (lane & 7) + 8 * ((lane >> 3) & 1);
    const int offVc = (lane >> 4) * 8;

    float O[32][4];
    #pragma unroll
    for (int i = 0; i < 32; i++)
        #pragma unroll
        for (int c = 0; c < 4; c++) O[i][c] = 0.f;
    float m0r = -1e30f, m1r = -1e30f, l0 = 0.f, l1 = 0.f;
    const int tr0 = t0 + 16 * w + (lane >> 2);
    const int tr1 = tr0 + 8;

    int s_begin = t0 - (WIN - 1); if (s_begin < 0) s_begin = 0;
    s_begin &= ~63;

    for (int s0 = s_begin; s0 <= t0 + BQ - 1; s0 += KT) {
        __syncthreads();
        for (int e = tid; e < 2048; e += 128) {
            int r = e >> 5, c = (e & 31) * 8;
            long g = (long)(s0 + r) * HH + c;
            *(uint4*)&Kh[r * DSTR + c] = *(const uint4*)(khg + g);
            *(uint4*)&Kl[r * DSTR + c] = *(const uint4*)(klg + g);
            *(uint4*)&Vh[r * DSTR + c] = *(const uint4*)(vhg + g);
            *(uint4*)&Vl[r * DSTR + c] = *(const uint4*)(vlg + g);
        }
        __syncthreads();

        // ---- S = Q K^T (bf16x3) ----
        float S[8][4];
        #pragma unroll
        for (int i = 0; i < 8; i++)
            #pragma unroll
            for (int c = 0; c < 4; c++) S[i][c] = 0.f;

        #pragma unroll
        for (int kc = 0; kc < 16; kc++) {
            uint32_t ah4[4], al4[4];
            LDSM4(ah4, QhB + (uint32_t)(offQ + kc * 16) * 2);
            LDSM4(al4, QlB + (uint32_t)(offQ + kc * 16) * 2);
            #pragma unroll
            for (int nb = 0; nb < 4; nb++) {
                uint32_t bh4[4], bl4[4];
                LDSM4(bh4, KhB + (uint32_t)(offK[nb] + kc * 16) * 2);
                LDSM4(bl4, KlB + (uint32_t)(offK[nb] + kc * 16) * 2);
                MMA16816(S[2*nb],   ah4, bh4[0], bh4[1]);
                MMA16816(S[2*nb],   ah4, bl4[0], bl4[1]);
                MMA16816(S[2*nb],   al4, bh4[0], bh4[1]);
                MMA16816(S[2*nb+1], ah4, bh4[2], bh4[3]);
                MMA16816(S[2*nb+1], ah4, bl4[2], bl4[3]);
                MMA16816(S[2*nb+1], al4, bh4[2], bh4[3]);
            }
        }

        // ---- mask + online softmax (rows fully in-warp) ----
        float rmax0 = -1e30f, rmax1 = -1e30f;
        #pragma unroll
        for (int nf = 0; nf < 8; nf++) {
            int c0 = s0 + nf * 8 + (lane & 3) * 2;
            if (!((c0     <= tr0) && (c0     > tr0 - WIN))) S[nf][0] = -1e30f;
            if (!((c0 + 1 <= tr0) && (c0 + 1 > tr0 - WIN))) S[nf][1] = -1e30f;
            if (!((c0     <= tr1) && (c0     > tr1 - WIN))) S[nf][2] = -1e30f;
            if (!((c0 + 1 <= tr1) && (c0 + 1 > tr1 - WIN))) S[nf][3] = -1e30f;
            rmax0 = fmaxf(rmax0, fmaxf(S[nf][0], S[nf][1]));
            rmax1 = fmaxf(rmax1, fmaxf(S[nf][2], S[nf][3]));
        }
        rmax0 = fmaxf(rmax0, __shfl_xor_sync(0xffffffffu, rmax0, 1));
        rmax0 = fmaxf(rmax0, __shfl_xor_sync(0xffffffffu, rmax0, 2));
        rmax1 = fmaxf(rmax1, __shfl_xor_sync(0xffffffffu, rmax1, 1));
        rmax1 = fmaxf(rmax1, __shfl_xor_sync(0xffffffffu, rmax1, 2));

        float mn0 = fmaxf(m0r, rmax0), mn1 = fmaxf(m1r, rmax1);
        float fac0 = __expf(m0r - mn0), fac1 = __expf(m1r - mn1);
        m0r = mn0; m1r = mn1;

        uint32_t pha[8][2], pla[8][2];
        float rs0 = 0.f, rs1 = 0.f;
        #pragma unroll
        for (int nf = 0; nf < 8; nf++) {
            float p0 = S[nf][0] > -1e29f ? __expf(S[nf][0] - mn0) : 0.f;
            float p1 = S[nf][1] > -1e29f ? __expf(S[nf][1] - mn0) : 0.f;
            float p2 = S[nf][2] > -1e29f ? __expf(S[nf][2] - mn1) : 0.f;
            float p3 = S[nf][3] > -1e29f ? __expf(S[nf][3] - mn1) : 0.f;
            rs0 += p0 + p1; rs1 += p2 + p3;
            uint32_t h01 = bf16x2_of(p0, p1);
            uint32_t h23 = bf16x2_of(p2, p3);
            pha[nf][0] = h01; pha[nf][1] = h23;
            pla[nf][0] = bf16x2_of(p0 - __uint_as_float(h01 << 16),
                                   p1 - __uint_as_float(h01 & 0xffff0000u));
            pla[nf][1] = bf16x2_of(p2 - __uint_as_float(h23 << 16),
                                   p3 - __uint_as_float(h23 & 0xffff0000u));
        }
        rs0 += __shfl_xor_sync(0xffffffffu, rs0, 1);
        rs0 += __shfl_xor_sync(0xffffffffu, rs0, 2);
        rs1 += __shfl_xor_sync(0xffffffffu, rs1, 1);
        rs1 += __shfl_xor_sync(0xffffffffu, rs1, 2);
        l0 = l0 * fac0 + rs0;
        l1 = l1 * fac1 + rs1;

        #pragma unroll
        for (int i = 0; i < 32; i++) {
            O[i][0] *= fac0; O[i][1] *= fac0;
            O[i][2] *= fac1; O[i][3] *= fac1;
        }

        // ---- O += P V (bf16x3, P fragments built in registers) ----
        #pragma unroll
        for (int kc = 0; kc < 4; kc++) {
            uint32_t pah4[4] = {pha[2*kc][0], pha[2*kc][1], pha[2*kc+1][0], pha[2*kc+1][1]};
            uint32_t pal4[4] = {pla[2*kc][0], pla[2*kc][1], pla[2*kc+1][0], pla[2*kc+1][1]};
            int vbase = (kc * 16 + offVr) * DSTR + offVc;
            #pragma unroll
            for (int hb = 0; hb < 16; hb++) {
                uint32_t v4h[4], v4l[4];
                LDSM4T(v4h, VhB + (uint32_t)(vbase + hb * 16) * 2);
                LDSM4T(v4l, VlB + (uint32_t)(vbase + hb * 16) * 2);
                MMA16816(O[2*hb],   pah4, v4h[0], v4h[1]);
                MMA16816(O[2*hb],   pah4, v4l[0], v4l[1]);
                MMA16816(O[2*hb],   pal4, v4h[0], v4h[1]);
                MMA16816(O[2*hb+1], pah4, v4h[2], v4h[3]);
                MMA16816(O[2*hb+1], pah4, v4l[2], v4l[3]);
                MMA16816(O[2*hb+1], pal4, v4h[2], v4h[3]);
            }
        }
    }

    // ---- epilogue: normalize, split hi/lo, write bf16 directly ----
    float inv0 = 1.f / l0, inv1 = 1.f / l1;
    long ma = (long)b * TSEQ + tr0;
    long mb = ma + 8;
    #pragma unroll
    for (int nf = 0; nf < 32; nf++) {
        int col = n * HH + nf * 8 + (lane & 3) * 2;
        float o0 = O[nf][0] * inv0, o1 = O[nf][1] * inv0;
        float o2 = O[nf][2] * inv1, o3 = O[nf][3] * inv1;
        uint32_t h01 = bf16x2_of(o0, o1);
        uint32_t h23 = bf16x2_of(o2, o3);
        uint32_t lo01 = bf16x2_of(o0 - __uint_as_float(h01 << 16),
                                  o1 - __uint_as_float(h01 & 0xffff0000u));
        uint32_t lo23 = bf16x2_of(o2 - __uint_as_float(h23 << 16),
                                  o3 - __uint_as_float(h23 & 0xffff0000u));
        *(uint32_t*)&ohp[ma * DD + col] = h01;
        *(uint32_t*)&ohp[mb * DD + col] = h23;
        *(uint32_t*)&olp[ma * DD + col] = lo01;
        *(uint32_t*)&olp[mb * DD + col] = lo23;
    }
}

// ---------------- launcher ---------------------------------------------------
extern "C" void kernel_launch(void* const* d_in, const int* in_sizes, int n_in,
                              void* d_out, int out_size) {
    const float* x    = (const float*)d_in[0];
    const int*   pos  = (const int*)  d_in[1];
    const float* q_w  = (const float*)d_in[2];
    const float* k_w  = (const float*)d_in[3];
    const float* v_w  = (const float*)d_in[4];
    const float* o_w  = (const float*)d_in[5];
    const float* qns  = (const float*)d_in[6];
    const float* kns  = (const float*)d_in[7];
    float* out = (float*)d_out;

    float *pq, *pk, *pv;
    bf16 *pxh, *pxl, *pah, *pal;
    bf16 *pqbh, *pqbl, *pkbh, *pkbl, *pvbh, *pvbl;
    bf16 *pwqh, *pwql, *pwkh, *pwkl, *pwvh, *pwvl, *pwoh, *pwol;
    cudaGetSymbolAddress((void**)&pq,   g_q);
    cudaGetSymbolAddress((void**)&pk,   g_k);
    cudaGetSymbolAddress((void**)&pv,   g_v);
    cudaGetSymbolAddress((void**)&pxh,  g_xh);
    cudaGetSymbolAddress((void**)&pxl,  g_xl);
    cudaGetSymbolAddress((void**)&pah,  g_ah);
    cudaGetSymbolAddress((void**)&pal,  g_al);
    cudaGetSymbolAddress((void**)&pqbh, g_qbh);
    cudaGetSymbolAddress((void**)&pqbl, g_qbl);
    cudaGetSymbolAddress((void**)&pkbh, g_kbh);
    cudaGetSymbolAddress((void**)&pkbl, g_kbl);
    cudaGetSymbolAddress((void**)&pvbh, g_vbh);
    cudaGetSymbolAddress((void**)&pvbl, g_vbl);
    cudaGetSymbolAddress((void**)&pwqh, g_wqh);
    cudaGetSymbolAddress((void**)&pwql, g_wql);
    cudaGetSymbolAddress((void**)&pwkh, g_wkh);
    cudaGetSymbolAddress((void**)&pwkl, g_wkl);
    cudaGetSymbolAddress((void**)&pwvh, g_wvh);
    cudaGetSymbolAddress((void**)&pwvl, g_wvl);
    cudaGetSymbolAddress((void**)&pwoh, g_woh);
    cudaGetSymbolAddress((void**)&pwol, g_wol);

    cudaFuncSetAttribute(gemm_mma,
                         cudaFuncAttributeMaxDynamicSharedMemorySize, GSMEM);
    cudaFuncSetAttribute(attn_mma,
                         cudaFuncAttributeMaxDynamicSharedMemorySize, ATTN_SMEM);

    // split x + weights into bf16 hi/lo (weights K-major transposed)
    cvt_hilo<<<(MT * DD) / 1024, 256>>>(x, pxh, pxl);
    transcvt<<<dim3(HH / 32, DD / 32, NQ),  dim3(32, 8)>>>(q_w, pwqh, pwql, DD, HH);
    transcvt<<<dim3(HH / 32, DD / 32, NKV), dim3(32, 8)>>>(k_w, pwkh, pwkl, DD, HH);
    transcvt<<<dim3(HH / 32, DD / 32, NKV), dim3(32, 8)>>>(v_w, pwvh, pwvl, DD, HH);
    transcvt<<<dim3(DD / 32, DD / 32, 1),   dim3(32, 8)>>>(o_w, pwoh, pwol, DD, DD);

    // Q/K/V projections (bf16x3 mma.sync) -> fp32
    gemm_mma<<<dim3(2, 32, NQ),  256, GSMEM>>>(pxh, pxl, pwqh, pwql, pq, HH,
                                               (long)HH * DD, (long)MT * HH);
    gemm_mma<<<dim3(2, 32, NKV), 256, GSMEM>>>(pxh, pxl, pwkh, pwkl, pk, HH,
                                               (long)HH * DD, (long)MT * HH);
    gemm_mma<<<dim3(2, 32, NKV), 256, GSMEM>>>(pxh, pxl, pwvh, pwvl, pv, HH,
                                               (long)HH * DD, (long)MT * HH);

    // RMSNorm + RoPE (+ q scale) -> bf16 hi/lo; V -> bf16 hi/lo
    normrope_kernel<<<dim3(MT, NQ + NKV), 64>>>(pq, pk, pqbh, pqbl, pkbh, pkbl,
                                                pos, qns, kns);
    cvt_hilo<<<((size_t)NKV * MT * HH) / 1024, 256>>>(pv, pvbh, pvbl);

    // windowed attention on tensor cores -> bf16 hi/lo (O-proj input)
    attn_mma<<<dim3(TSEQ / BQ, NQ, 2), 128, ATTN_SMEM>>>(pqbh, pqbl, pkbh, pkbl,
                                                         pvbh, pvbl, pah, pal);

    // output projection
    gemm_mma<<<dim3(16, 32, 1), 256, GSMEM>>>(pah, pal, pwoh, pwol, out, DD, 0, 0);
}